// round 4
// baseline (speedup 1.0000x reference)
#include <cuda_runtime.h>

// ---------------------------------------------------------------------------
// KappaGCN forward: two kappa_layers + hyperbolic logits + aggregation.
// Heavy work = 3 GEMMs against A_hat [8192 x 8192]:
//   P1 = A @ [gamma*XW | gamma-1 | 1 | pad]  (40 cols)   (layer 1)
//   P2 = A @ [ ... ]                          (40 cols)   (layer 2)
//   OUT = A @ logits                          (16 cols)
// GEMMs use packed fma.rn.f32x2 (sm_100+) -> 2x fp32 FMA rate.
// Split-K=8 with private partial slices (no atomics), reduced in epilogues.
// ---------------------------------------------------------------------------

#define FULLMASK 0xffffffffu

constexpr int N   = 8192;
constexpr int D   = 32;
constexpr int C   = 16;
constexpr int NC1 = 40;     // padded column count for layer GEMMs (34 real)
constexpr int KSPLIT = 8;
constexpr int BM  = 128;
constexpr int BK  = 32;
constexpr int GT  = 256;    // GEMM threads per block

// ---- scratch (static device arrays; no allocation) ----
__device__ __align__(256) float g_M [N * NC1];              // 1.31 MB
__device__ __align__(256) float g_Pp[KSPLIT * N * NC1];     // 10.5 MB
__device__ __align__(256) float g_X2[N * D];                // 1.05 MB
__device__ __align__(256) float g_L [N * C];                // 0.52 MB
__device__ __align__(256) float g_Po[KSPLIT * N * C];       // 4.2 MB

// ---- helpers ----
__device__ __forceinline__ float wsum(float v) {
#pragma unroll
    for (int o = 16; o > 0; o >>= 1) v += __shfl_xor_sync(FULLMASK, v, o);
    return v;
}

// artanh with reference clipping: clip(x, -1+1e-7, 1-1e-7). float32(1-1e-7)=0.99999988f
__device__ __forceinline__ float artanh_c(float v) {
    v = fminf(fmaxf(v, -0.99999988f), 0.99999988f);
    return atanhf(v);
}

// =============================================================================
// prep: per row i of input X:
//   XW = mobius_matvec(W, x); gamma = 2/max(1-||XW||^2, 1e-15)
//   M[i, 0:32] = gamma*XW;  M[i,32] = gamma-1;  M[i,33] = 1;  M[i,34:40] = 0
// one warp per row, lane = feature dim.
// =============================================================================
__global__ void prep_kernel(const float* __restrict__ X0,
                            const float* __restrict__ W,
                            int useScratch)
{
    __shared__ float Ws[D][D + 1];
    const int tid = threadIdx.x;
    for (int i = tid; i < D * D; i += blockDim.x)
        Ws[i >> 5][i & 31] = W[i];
    __syncthreads();

    const int lane = tid & 31;
    const int row  = blockIdx.x * (blockDim.x >> 5) + (tid >> 5);
    const float* Xin = useScratch ? g_X2 : X0;

    float x  = Xin[row * D + lane];
    float xn = sqrtf(fmaxf(wsum(x * x), 1e-30f));

    float mx = 0.f;
#pragma unroll
    for (int d = 0; d < D; ++d)
        mx = fmaf(__shfl_sync(FULLMASK, x, d), Ws[d][lane], mx);

    float mxn = sqrtf(fmaxf(wsum(mx * mx), 1e-30f));
    float sc  = tanhf(mxn / xn * artanh_c(xn)) / mxn;
    float xw  = sc * mx;
    float xw2 = wsum(xw * xw);
    float gamma = 2.f / fmaxf(1.f - xw2, 1e-15f);

    float* Mrow = g_M + row * NC1;
    Mrow[lane] = gamma * xw;
    if (lane == 0) { Mrow[32] = gamma - 1.f; Mrow[33] = 1.f; }
    if (lane >= 26) Mrow[34 + (lane - 26)] = 0.f;   // zero pad cols 34..39
}

// =============================================================================
// GEMM: P[ks][r][n] = sum_{k in split ks} A[r,k] * M[k,n]
// BM=128 rows x NC cols per block, BK=32, 256 threads, split-K via blockIdx.y.
// Thread computes 2 rows x (NC/8) column-pairs using packed f32x2 FMA.
// =============================================================================
template <int NC>
__global__ void __launch_bounds__(GT) gemm_kernel(const float* __restrict__ A)
{
    static_assert(NC % 8 == 0, "NC must be multiple of 8");
    constexpr int TNP  = NC / 8;             // col-pairs per thread (5 or 2)
    constexpr int MREG = BK * NC / GT;       // staged M floats per thread (5 or 2)

    __shared__ __align__(16) float As[BK][BM + 2];   // pitch 130 (even, low conflict)
    __shared__ __align__(16) float Ms[BK * NC];

    const float* Mg = (NC == NC1) ? g_M  : g_L;
    float*       Pg = (NC == NC1) ? g_Pp : g_Po;

    const int tid  = threadIdx.x;
    const int row0 = blockIdx.x * BM;
    const int kb0  = blockIdx.y * (N / KSPLIT);

    const int rg = tid & 63;        // owns rows 2*rg, 2*rg+1
    const int cp = tid >> 6;        // col-pair phase 0..3

    const int arow = tid >> 3;      // A-tile load: row within 32-row group
    const int ak   = (tid & 7) << 2;// A-tile load: k offset (float4)

    unsigned long long acc[2][TNP];
#pragma unroll
    for (int t = 0; t < 2; ++t)
#pragma unroll
        for (int p = 0; p < TNP; ++p) acc[t][p] = 0ull;

    float4 aReg[4];
    float  mReg[MREG];
    const float4* A4 = reinterpret_cast<const float4*>(A);

    // prologue: stage tile 0
    {
        const int kb = kb0;
#pragma unroll
        for (int i = 0; i < 4; ++i)
            aReg[i] = A4[((size_t)(row0 + arow + i * 32) * N + kb + ak) >> 2];
#pragma unroll
        for (int i = 0; i < MREG; ++i)
            mReg[i] = Mg[kb * NC + i * GT + tid];
    }

    const int iters = (N / KSPLIT) / BK;   // 32
    for (int it = 0; it < iters; ++it) {
        __syncthreads();
        // commit staged tile to smem (A transposed: As[k][row])
#pragma unroll
        for (int i = 0; i < 4; ++i) {
            const int r = arow + i * 32;
            As[ak + 0][r] = aReg[i].x;
            As[ak + 1][r] = aReg[i].y;
            As[ak + 2][r] = aReg[i].z;
            As[ak + 3][r] = aReg[i].w;
        }
#pragma unroll
        for (int i = 0; i < MREG; ++i) Ms[i * GT + tid] = mReg[i];
        __syncthreads();

        // prefetch next tile while computing this one
        if (it + 1 < iters) {
            const int kb = kb0 + (it + 1) * BK;
#pragma unroll
            for (int i = 0; i < 4; ++i)
                aReg[i] = A4[((size_t)(row0 + arow + i * 32) * N + kb + ak) >> 2];
#pragma unroll
            for (int i = 0; i < MREG; ++i)
                mReg[i] = Mg[kb * NC + i * GT + tid];
        }

        // compute: packed-pair FMAs
#pragma unroll
        for (int k = 0; k < BK; ++k) {
            unsigned long long a2 =
                *reinterpret_cast<const unsigned long long*>(&As[k][2 * rg]);
            unsigned int alo, ahi;
            asm("mov.b64 {%0,%1}, %2;" : "=r"(alo), "=r"(ahi) : "l"(a2));
            unsigned long long aa0, aa1;
            asm("mov.b64 %0, {%1,%1};" : "=l"(aa0) : "r"(alo));
            asm("mov.b64 %0, {%1,%1};" : "=l"(aa1) : "r"(ahi));
#pragma unroll
            for (int p = 0; p < TNP; ++p) {
                unsigned long long mm =
                    *reinterpret_cast<const unsigned long long*>(
                        &Ms[k * NC + 2 * (cp + 4 * p)]);
                asm("fma.rn.f32x2 %0, %1, %2, %0;" : "+l"(acc[0][p]) : "l"(aa0), "l"(mm));
                asm("fma.rn.f32x2 %0, %1, %2, %0;" : "+l"(acc[1][p]) : "l"(aa1), "l"(mm));
            }
        }
    }

    // epilogue: write this split's partial (8B stores, aligned: NC even)
    float* dst0 = Pg + (size_t)blockIdx.y * N * NC;
#pragma unroll
    for (int t = 0; t < 2; ++t) {
        const int row = row0 + 2 * rg + t;
#pragma unroll
        for (int p = 0; p < TNP; ++p)
            *reinterpret_cast<unsigned long long*>(
                dst0 + (size_t)row * NC + 2 * (cp + 4 * p)) = acc[t][p];
    }
}

// =============================================================================
// post: reduce split-K partials, then
//   denom clamp, a_mean = msm(0.5, nom/denom), AXW = msm(alpha, a_mean),
//   X_out = expmap0(relu(logmap0(AXW))).  One warp per row.
// =============================================================================
__global__ void post_kernel()
{
    const int tid  = threadIdx.x;
    const int lane = tid & 31;
    const int row  = blockIdx.x * (blockDim.x >> 5) + (tid >> 5);

    float nom = 0.f, den = 0.f, alp = 0.f;
#pragma unroll
    for (int s = 0; s < KSPLIT; ++s) {
        const float* pr = g_Pp + ((size_t)s * N + row) * NC1;
        nom += pr[lane];
        den += pr[32];
        alp += pr[33];
    }
    den = (den >= 0.f) ? fmaxf(den, 1e-10f) : fminf(den, -1e-10f);

    float v  = nom / den;
    float vn = sqrtf(fmaxf(wsum(v * v), 1e-30f));

    // a_mean = tanh(0.5*artanh(vn)) * v/vn
    float t  = tanhf(0.5f * artanh_c(vn));
    float am = t * (v / vn);
    float amn = sqrtf(fmaxf(wsum(am * am), 1e-30f));

    // AXW = tanh(alpha*artanh(||a_mean||)) * a_mean/||a_mean||
    float u   = tanhf(alp * artanh_c(amn));
    float axw = u * (am / amn);
    float axwn = sqrtf(fmaxf(wsum(axw * axw), 1e-30f));

    // logmap0 -> relu -> expmap0
    float l  = artanh_c(axwn) * (axw / axwn);
    float r  = fmaxf(l, 0.f);
    float rn = sqrtf(fmaxf(wsum(r * r), 1e-30f));
    g_X2[row * D + lane] = tanhf(rn) * (r / rn);
}

// =============================================================================
// logits: hyperbolic MLR logits per (row, class). One warp per row.
// =============================================================================
__global__ void logits_kernel(const float* __restrict__ Wl,   // [D][C]
                              const float* __restrict__ pks)  // [C][D]
{
    __shared__ float bs[C][D];
    __shared__ float ws[C][D];          // ws[c][d] = Wl[d][c]
    __shared__ float an_s[C], lam_s[C], b2_s[C];

    const int tid = threadIdx.x;
    for (int i = tid; i < C * D; i += blockDim.x) {
        const int c = i >> 5, d = i & 31;
        bs[c][d] = pks[i];
        ws[c][d] = Wl[d * C + c];
    }
    __syncthreads();
    if (tid < C) {
        float s2 = 0.f, b2 = 0.f;
        for (int d = 0; d < D; ++d) {
            s2 += ws[tid][d] * ws[tid][d];
            b2 += bs[tid][d] * bs[tid][d];
        }
        an_s[tid]  = fmaxf(sqrtf(s2), 1e-10f);
        b2_s[tid]  = b2;
        lam_s[tid] = 2.f / fmaxf(1.f - b2, 1e-15f);
    }
    __syncthreads();

    const int lane = tid & 31;
    const int row  = blockIdx.x * (blockDim.x >> 5) + (tid >> 5);

    float x  = g_X2[row * D + lane];
    float y2 = wsum(x * x);

    float myLogit = 0.f;
#pragma unroll 1
    for (int c = 0; c < C; ++c) {
        float bd  = bs[c][lane];
        float bx  = wsum(bd * x);
        float b2  = b2_s[c];
        float c1  = 1.f - 2.f * bx + y2;     // (1 - 2K xy - K y2) with x = -b
        float c2  = 1.f - b2;                // (1 + K x2)
        float dd  = fmaxf(1.f - 2.f * bx + b2 * y2, 1e-15f);
        float z   = (c2 * x - c1 * bd) / dd;
        float za  = wsum(z * ws[c][lane]);
        float zn  = fmaxf(sqrtf(fmaxf(wsum(z * z), 1e-30f)), 1e-10f);
        float an  = an_s[c];
        float dist = asinhf(2.f * za / ((1.f - zn * zn) * an));
        float lg  = lam_s[c] * an * dist;
        if (lane == c) myLogit = lg;
    }
    if (lane < C) g_L[row * C + lane] = myLogit;
}

// =============================================================================
// reduce split-K partials of the final A @ logits into d_out
// =============================================================================
__global__ void reduce_kernel(float* __restrict__ out)
{
    const int i = blockIdx.x * blockDim.x + threadIdx.x;  // < N*C
    float s = 0.f;
#pragma unroll
    for (int k = 0; k < KSPLIT; ++k) s += g_Po[(size_t)k * N * C + i];
    out[i] = s;
}

// =============================================================================
// launch
// =============================================================================
extern "C" void kernel_launch(void* const* d_in, const int* in_sizes, int n_in,
                              void* d_out, int out_size)
{
    const float* X  = (const float*)d_in[0];   // [N, D]
    const float* A  = (const float*)d_in[1];   // [N, N]
    const float* W1 = (const float*)d_in[2];   // [D, D]
    const float* W2 = (const float*)d_in[3];   // [D, D]
    const float* Wl = (const float*)d_in[4];   // [D, C]
    const float* pk = (const float*)d_in[5];   // [C, D]

    const dim3 ggrid(N / BM, KSPLIT);          // (64, 8)
    const int  rgrid = N / (256 / 32);         // 1024 blocks, warp-per-row

    // layer 1
    prep_kernel<<<rgrid, 256>>>(X, W1, 0);
    gemm_kernel<NC1><<<ggrid, GT>>>(A);
    post_kernel<<<rgrid, 256>>>();

    // layer 2
    prep_kernel<<<rgrid, 256>>>(X, W2, 1);
    gemm_kernel<NC1><<<ggrid, GT>>>(A);
    post_kernel<<<rgrid, 256>>>();

    // logits + aggregation
    logits_kernel<<<rgrid, 256>>>(Wl, pk);
    gemm_kernel<C><<<ggrid, GT>>>(A);
    reduce_kernel<<<(N * C) / 256, 256>>>((float*)d_out);
}

// round 9
// speedup vs baseline: 1.9741x; 1.9741x over previous
#include <cuda_runtime.h>
#include <cuda_bf16.h>
#include <cstdint>

#define FULLMASK 0xffffffffu

constexpr int N = 8192, D = 32, C = 16;
constexpr int NC1 = 40;                   // stored cols for layer GEMMs (34 real)
constexpr int KSPLIT = 4;
constexpr int BM = 128, BK = 64;
constexpr int TILES = (N / KSPLIT) / BK;  // 32
constexpr int PITCH = 72;                 // smem row pitch in bf16 (144 B)

// ---- scratch (static device arrays; zero-initialized, never allocated) ----
__device__ __align__(256) __nv_bfloat16 g_MtH[64 * N];      // B^T hi; rows 34..63 stay 0
__device__ __align__(256) __nv_bfloat16 g_MtL[64 * N];      // B^T lo; rows 34..63 stay 0
__device__ __align__(256) float g_Pp[KSPLIT * N * NC1];     // layer partials
__device__ __align__(256) float g_Po[KSPLIT * N * C];       // logits partials
__device__ __align__(256) float g_X2[N * D];                // layer outputs

__device__ __forceinline__ float wsum(float v) {
#pragma unroll
    for (int o = 16; o > 0; o >>= 1) v += __shfl_xor_sync(FULLMASK, v, o);
    return v;
}
__device__ __forceinline__ float artanh_c(float v) {
    v = fminf(fmaxf(v, -0.99999988f), 0.99999988f);
    return atanhf(v);
}
// write hi/lo double-bf16 decomposition of v
__device__ __forceinline__ void store_hl(int idx, float v) {
    __nv_bfloat16 h = __float2bfloat16_rn(v);
    g_MtH[idx] = h;
    g_MtL[idx] = __float2bfloat16_rn(v - __bfloat162float(h));
}

// ============================ prep (layer input -> B^T hi/lo) ===============
__global__ void prep_kernel(const float* __restrict__ X0,
                            const float* __restrict__ W, int useScratch)
{
    __shared__ float Ws[D][D + 1];
    const int tid = threadIdx.x;
    for (int i = tid; i < D * D; i += blockDim.x) Ws[i >> 5][i & 31] = W[i];
    __syncthreads();

    const int lane = tid & 31;
    const int row = blockIdx.x * (blockDim.x >> 5) + (tid >> 5);
    const float* Xin = useScratch ? g_X2 : X0;

    float x = Xin[row * D + lane];
    float xn = sqrtf(fmaxf(wsum(x * x), 1e-30f));
    float mx = 0.f;
#pragma unroll
    for (int d = 0; d < D; ++d)
        mx = fmaf(__shfl_sync(FULLMASK, x, d), Ws[d][lane], mx);
    float mxn = sqrtf(fmaxf(wsum(mx * mx), 1e-30f));
    float xw = tanhf(mxn / xn * artanh_c(xn)) / mxn * mx;
    float gamma = 2.f / fmaxf(1.f - wsum(xw * xw), 1e-15f);

    store_hl(lane * N + row, gamma * xw);
    if (lane == 0) store_hl(32 * N + row, gamma - 1.f);
    if (lane == 1) store_hl(33 * N + row, 1.f);
}

// ============================ double-bf16 HMMA GEMM =========================
// P[split][r][c] = sum_{k in split} A[r,k] * Mt[c][k]
// A and B each split hi/lo; product = hiA*hiB + hiA*loB + loA*hiB.
// BM=128 rows/CTA, BK=64, 8 warps (16 rows each), NT n8-tiles (N = NT*8).
template <int NT>
__global__ void __launch_bounds__(256, 2) gemm_mma(const float* __restrict__ A)
{
    constexpr int NR = NT * 8;        // B rows (output cols)
    constexpr int BU = NR * 8;        // uint4 chunks per B tile

    __shared__ __nv_bfloat16 AsH[BM * PITCH];   // 18.0 KB
    __shared__ __nv_bfloat16 AsL[BM * PITCH];   // 18.0 KB
    __shared__ __nv_bfloat16 BsH[NR * PITCH];   // 5.6 / 2.25 KB
    __shared__ __nv_bfloat16 BsL[NR * PITCH];

    const int tid = threadIdx.x, wid = tid >> 5, lane = tid & 31;
    const int row0 = blockIdx.x * BM;
    const size_t kb0 = (size_t)blockIdx.y * (N / KSPLIT);

    // A global: thread covers rows (tid>>4)+16p, float4 chunk (tid&15)
    const float4* af4 = reinterpret_cast<const float4*>(
        A + ((size_t)(row0 + (tid >> 4)) * N + kb0)) + (tid & 15);
    // B global: uint4 u -> row u>>3, chunk u&7 (8 bf16 each)
    const char* bbH = reinterpret_cast<const char*>(g_MtH + kb0);
    const char* bbL = reinterpret_cast<const char*>(g_MtL + kb0);
    const size_t bo0 = (size_t)(tid >> 3) * N * 2 + (tid & 7) * 16;
    const size_t bo1 = (size_t)((tid + 256) >> 3) * N * 2 + (tid & 7) * 16;

    // smem store offsets
    const int asOff = (tid >> 4) * PITCH + (tid & 15) * 4;
    const int bsOff0 = (tid >> 3) * PITCH + (tid & 7) * 8;
    const int bsOff1 = ((tid + 256) >> 3) * PITCH + (tid & 7) * 8;

    float acc[NT][4];
#pragma unroll
    for (int j = 0; j < NT; ++j)
#pragma unroll
        for (int q = 0; q < 4; ++q) acc[j][q] = 0.f;

    float4 ar[8];
    uint4 brH0, brH1, brL0, brL1;
#pragma unroll
    for (int p = 0; p < 8; ++p) ar[p] = af4[(size_t)p * 32768];
    brH0 = *reinterpret_cast<const uint4*>(bbH + bo0);
    brL0 = *reinterpret_cast<const uint4*>(bbL + bo0);
    if (BU > 256 && tid < BU - 256) {
        brH1 = *reinterpret_cast<const uint4*>(bbH + bo1);
        brL1 = *reinterpret_cast<const uint4*>(bbL + bo1);
    }

    for (int t = 0; t < TILES; ++t) {
        __syncthreads();   // previous compute done reading smem
        // commit A tile: fp32 -> hi bf16x2 + lo bf16x2
#pragma unroll
        for (int p = 0; p < 8; ++p) {
            uint32_t h0, h1, l0, l1;
            asm("cvt.rn.bf16x2.f32 %0, %1, %2;" : "=r"(h0) : "f"(ar[p].y), "f"(ar[p].x));
            asm("cvt.rn.bf16x2.f32 %0, %1, %2;" : "=r"(h1) : "f"(ar[p].w), "f"(ar[p].z));
            float hx = __uint_as_float(h0 << 16);
            float hy = __uint_as_float(h0 & 0xFFFF0000u);
            float hz = __uint_as_float(h1 << 16);
            float hw = __uint_as_float(h1 & 0xFFFF0000u);
            asm("cvt.rn.bf16x2.f32 %0, %1, %2;" : "=r"(l0)
                : "f"(ar[p].y - hy), "f"(ar[p].x - hx));
            asm("cvt.rn.bf16x2.f32 %0, %1, %2;" : "=r"(l1)
                : "f"(ar[p].w - hw), "f"(ar[p].z - hz));
            *reinterpret_cast<uint2*>(&AsH[asOff + p * 16 * PITCH]) = make_uint2(h0, h1);
            *reinterpret_cast<uint2*>(&AsL[asOff + p * 16 * PITCH]) = make_uint2(l0, l1);
        }
        // commit B tiles
        if (tid < BU) {
            *reinterpret_cast<uint4*>(&BsH[bsOff0]) = brH0;
            *reinterpret_cast<uint4*>(&BsL[bsOff0]) = brL0;
        }
        if (BU > 256 && tid < BU - 256) {
            *reinterpret_cast<uint4*>(&BsH[bsOff1]) = brH1;
            *reinterpret_cast<uint4*>(&BsL[bsOff1]) = brL1;
        }
        __syncthreads();

        // prefetch next tile (LDG latency hidden by compute below)
        if (t + 1 < TILES) {
            const float4* ap = af4 + (size_t)(t + 1) * 16;
#pragma unroll
            for (int p = 0; p < 8; ++p) ar[p] = ap[(size_t)p * 32768];
            const size_t bshift = (size_t)(t + 1) * 128;
            brH0 = *reinterpret_cast<const uint4*>(bbH + bshift + bo0);
            brL0 = *reinterpret_cast<const uint4*>(bbL + bshift + bo0);
            if (BU > 256 && tid < BU - 256) {
                brH1 = *reinterpret_cast<const uint4*>(bbH + bshift + bo1);
                brL1 = *reinterpret_cast<const uint4*>(bbL + bshift + bo1);
            }
        }

        // compute: 4 k-steps of m16n8k16, 3 products each
        const int aoff = (wid * 16 + (lane >> 2)) * PITCH + (lane & 3) * 2;
        const int boff = (lane >> 2) * PITCH + (lane & 3) * 2;
#pragma unroll
        for (int s = 0; s < 4; ++s) {
            uint32_t ah0 = *reinterpret_cast<const uint32_t*>(&AsH[aoff + s * 16]);
            uint32_t ah1 = *reinterpret_cast<const uint32_t*>(&AsH[aoff + s * 16 + 8 * PITCH]);
            uint32_t ah2 = *reinterpret_cast<const uint32_t*>(&AsH[aoff + s * 16 + 8]);
            uint32_t ah3 = *reinterpret_cast<const uint32_t*>(&AsH[aoff + s * 16 + 8 * PITCH + 8]);
            uint32_t al0 = *reinterpret_cast<const uint32_t*>(&AsL[aoff + s * 16]);
            uint32_t al1 = *reinterpret_cast<const uint32_t*>(&AsL[aoff + s * 16 + 8 * PITCH]);
            uint32_t al2 = *reinterpret_cast<const uint32_t*>(&AsL[aoff + s * 16 + 8]);
            uint32_t al3 = *reinterpret_cast<const uint32_t*>(&AsL[aoff + s * 16 + 8 * PITCH + 8]);
#pragma unroll
            for (int j = 0; j < NT; ++j) {
                uint32_t bh0 = *reinterpret_cast<const uint32_t*>(&BsH[boff + j * 8 * PITCH + s * 16]);
                uint32_t bh1 = *reinterpret_cast<const uint32_t*>(&BsH[boff + j * 8 * PITCH + s * 16 + 8]);
                uint32_t bl0 = *reinterpret_cast<const uint32_t*>(&BsL[boff + j * 8 * PITCH + s * 16]);
                uint32_t bl1 = *reinterpret_cast<const uint32_t*>(&BsL[boff + j * 8 * PITCH + s * 16 + 8]);
                asm volatile(
                    "mma.sync.aligned.m16n8k16.row.col.f32.bf16.bf16.f32 "
                    "{%0,%1,%2,%3}, {%4,%5,%6,%7}, {%8,%9}, {%0,%1,%2,%3};"
                    : "+f"(acc[j][0]), "+f"(acc[j][1]), "+f"(acc[j][2]), "+f"(acc[j][3])
                    : "r"(ah0), "r"(ah1), "r"(ah2), "r"(ah3), "r"(bl0), "r"(bl1));
                asm volatile(
                    "mma.sync.aligned.m16n8k16.row.col.f32.bf16.bf16.f32 "
                    "{%0,%1,%2,%3}, {%4,%5,%6,%7}, {%8,%9}, {%0,%1,%2,%3};"
                    : "+f"(acc[j][0]), "+f"(acc[j][1]), "+f"(acc[j][2]), "+f"(acc[j][3])
                    : "r"(al0), "r"(al1), "r"(al2), "r"(al3), "r"(bh0), "r"(bh1));
                asm volatile(
                    "mma.sync.aligned.m16n8k16.row.col.f32.bf16.bf16.f32 "
                    "{%0,%1,%2,%3}, {%4,%5,%6,%7}, {%8,%9}, {%0,%1,%2,%3};"
                    : "+f"(acc[j][0]), "+f"(acc[j][1]), "+f"(acc[j][2]), "+f"(acc[j][3])
                    : "r"(ah0), "r"(ah1), "r"(ah2), "r"(ah3), "r"(bh0), "r"(bh1));
            }
        }
    }

    // epilogue: write split partials (8B stores)
    float* Pg = (NT == 5) ? g_Pp : g_Po;
    constexpr int NOUT = NR;
    const int r0 = row0 + wid * 16 + (lane >> 2);
    const int cb = (lane & 3) * 2;
    float* base = Pg + (size_t)blockIdx.y * N * NOUT;
#pragma unroll
    for (int j = 0; j < NT; ++j) {
        *reinterpret_cast<float2*>(base + (size_t)r0 * NOUT + j * 8 + cb) =
            make_float2(acc[j][0], acc[j][1]);
        *reinterpret_cast<float2*>(base + (size_t)(r0 + 8) * NOUT + j * 8 + cb) =
            make_float2(acc[j][2], acc[j][3]);
    }
}

// ============================ post (gyromidpoint + sigma) ===================
__global__ void post_kernel()
{
    const int tid = threadIdx.x, lane = tid & 31;
    const int row = blockIdx.x * (blockDim.x >> 5) + (tid >> 5);

    float nom = 0.f, den = 0.f, alp = 0.f;
#pragma unroll
    for (int s = 0; s < KSPLIT; ++s) {
        const float* pr = g_Pp + ((size_t)s * N + row) * NC1;
        nom += pr[lane]; den += pr[32]; alp += pr[33];
    }
    den = (den >= 0.f) ? fmaxf(den, 1e-10f) : fminf(den, -1e-10f);

    float v = nom / den;
    float vn = sqrtf(fmaxf(wsum(v * v), 1e-30f));
    float am = tanhf(0.5f * artanh_c(vn)) * (v / vn);
    float amn = sqrtf(fmaxf(wsum(am * am), 1e-30f));
    float axw = tanhf(alp * artanh_c(amn)) * (am / amn);
    float axwn = sqrtf(fmaxf(wsum(axw * axw), 1e-30f));
    float r = fmaxf(artanh_c(axwn) * (axw / axwn), 0.f);
    float rn = sqrtf(fmaxf(wsum(r * r), 1e-30f));
    g_X2[row * D + lane] = tanhf(rn) * (r / rn);
}

// ============================ logits -> B^T hi/lo ===========================
__global__ void logits_kernel(const float* __restrict__ Wl,
                              const float* __restrict__ pks)
{
    __shared__ float bs[C][D], ws[C][D];
    __shared__ float an_s[C], lam_s[C], b2_s[C];
    const int tid = threadIdx.x;
    for (int i = tid; i < C * D; i += blockDim.x) {
        const int c = i >> 5, d = i & 31;
        bs[c][d] = pks[i];
        ws[c][d] = Wl[d * C + c];
    }
    __syncthreads();
    if (tid < C) {
        float s2 = 0.f, b2 = 0.f;
        for (int d = 0; d < D; ++d) { s2 += ws[tid][d] * ws[tid][d]; b2 += bs[tid][d] * bs[tid][d]; }
        an_s[tid] = fmaxf(sqrtf(s2), 1e-10f);
        b2_s[tid] = b2;
        lam_s[tid] = 2.f / fmaxf(1.f - b2, 1e-15f);
    }
    __syncthreads();

    const int lane = tid & 31;
    const int row = blockIdx.x * (blockDim.x >> 5) + (tid >> 5);
    float x = g_X2[row * D + lane];
    float y2 = wsum(x * x);

    float myLogit = 0.f;
#pragma unroll 1
    for (int c = 0; c < C; ++c) {
        float bd = bs[c][lane];
        float bx = wsum(bd * x);
        float b2 = b2_s[c];
        float c1 = 1.f - 2.f * bx + y2;
        float c2 = 1.f - b2;
        float dd = fmaxf(1.f - 2.f * bx + b2 * y2, 1e-15f);
        float z = (c2 * x - c1 * bd) / dd;
        float za = wsum(z * ws[c][lane]);
        float zn = fmaxf(sqrtf(fmaxf(wsum(z * z), 1e-30f)), 1e-10f);
        float dist = asinhf(2.f * za / ((1.f - zn * zn) * an_s[c]));
        float lg = lam_s[c] * an_s[c] * dist;
        if (lane == c) myLogit = lg;
    }
    if (lane < C) store_hl(lane * N + row, myLogit);
}

// ============================ final reduce ==================================
__global__ void reduce_kernel(float* __restrict__ out)
{
    const int i = blockIdx.x * blockDim.x + threadIdx.x;  // < N*C
    float s = 0.f;
#pragma unroll
    for (int k = 0; k < KSPLIT; ++k) s += g_Po[(size_t)k * N * C + i];
    out[i] = s;
}

// ============================ launch ========================================
extern "C" void kernel_launch(void* const* d_in, const int* in_sizes, int n_in,
                              void* d_out, int out_size)
{
    const float* X  = (const float*)d_in[0];
    const float* A  = (const float*)d_in[1];
    const float* W1 = (const float*)d_in[2];
    const float* W2 = (const float*)d_in[3];
    const float* Wl = (const float*)d_in[4];
    const float* pk = (const float*)d_in[5];

    const dim3 ggrid(N / BM, KSPLIT);   // (64, 4)
    const int rgrid = N / 8;            // warp-per-row kernels

    prep_kernel<<<rgrid, 256>>>(X, W1, 0);
    gemm_mma<5><<<ggrid, 256>>>(A);
    post_kernel<<<rgrid, 256>>>();

    prep_kernel<<<rgrid, 256>>>(X, W2, 1);
    gemm_mma<5><<<ggrid, 256>>>(A);
    post_kernel<<<rgrid, 256>>>();

    logits_kernel<<<rgrid, 256>>>(Wl, pk);
    gemm_mma<2><<<ggrid, 256>>>(A);
    reduce_kernel<<<(N * C) / 256, 256>>>((float*)d_out);
}

// round 13
// speedup vs baseline: 2.0625x; 1.0448x over previous
#include <cuda_runtime.h>
#include <cuda_bf16.h>
#include <cstdint>

#define FULLMASK 0xffffffffu

constexpr int N = 8192, D = 32, C = 16;
constexpr int NC1 = 40;                   // stored cols for layer GEMMs (34 real)
constexpr int KSPLIT = 4;
constexpr int BM = 128, BK = 64;
constexpr int TILES = (N / KSPLIT) / BK;  // 32
constexpr int PITCH = 72;                 // smem row pitch in bf16 (144 B)
constexpr int ASTAGE = BM * PITCH;        // bf16 elems per A stage (9216)

// ---- scratch (static device arrays; zero-initialized, never allocated) ----
__device__ __align__(256) __nv_bfloat16 g_MtH[64 * N];      // B^T hi; rows 34..63 stay 0
__device__ __align__(256) __nv_bfloat16 g_MtL[64 * N];      // B^T lo; rows 34..63 stay 0
__device__ __align__(256) float g_Pp[KSPLIT * N * NC1];     // layer partials
__device__ __align__(256) float g_Po[KSPLIT * N * C];       // logits partials

__device__ __forceinline__ float wsum(float v) {
#pragma unroll
    for (int o = 16; o > 0; o >>= 1) v += __shfl_xor_sync(FULLMASK, v, o);
    return v;
}
__device__ __forceinline__ float artanh_c(float v) {
    v = fminf(fmaxf(v, -0.99999988f), 0.99999988f);
    return atanhf(v);
}

// ---- staged transposed hi/lo stores: [col][8 rows], flushed as 16B chunks --
__device__ __forceinline__ void stage_hl(__nv_bfloat16 (*tH)[8],
                                         __nv_bfloat16 (*tL)[8],
                                         int col, int w, float v)
{
    __nv_bfloat16 h = __float2bfloat16_rn(v);
    tH[col][w] = h;
    tL[col][w] = __float2bfloat16_rn(v - __bfloat162float(h));
}
template <int NCOLS>
__device__ __forceinline__ void store_cols_t(__nv_bfloat16 (*tH)[8],
                                             __nv_bfloat16 (*tL)[8],
                                             int tid, int row0)
{
    __syncthreads();
    if (tid < NCOLS) {
        *reinterpret_cast<uint4*>(&g_MtH[(size_t)tid * N + row0]) =
            *reinterpret_cast<const uint4*>(&tH[tid][0]);
        *reinterpret_cast<uint4*>(&g_MtL[(size_t)tid * N + row0]) =
            *reinterpret_cast<const uint4*>(&tL[tid][0]);
    }
}

// ---- prep math: x (lane=dim) -> stage gamma*XW | gamma-1 | 1 ---------------
__device__ __forceinline__ void prep_math(const float (*Ws)[D + 1], float x,
                                          int lane, int w,
                                          __nv_bfloat16 (*tH)[8],
                                          __nv_bfloat16 (*tL)[8])
{
    float xn = sqrtf(fmaxf(wsum(x * x), 1e-30f));
    float mx = 0.f;
#pragma unroll
    for (int d = 0; d < D; ++d)
        mx = fmaf(__shfl_sync(FULLMASK, x, d), Ws[d][lane], mx);
    float mxn = sqrtf(fmaxf(wsum(mx * mx), 1e-30f));
    float xw = tanhf(mxn / xn * artanh_c(xn)) / mxn * mx;
    float gamma = 2.f / fmaxf(1.f - wsum(xw * xw), 1e-15f);

    stage_hl(tH, tL, lane, w, gamma * xw);
    if (lane == 0) stage_hl(tH, tL, 32, w, gamma - 1.f);
    if (lane == 1) stage_hl(tH, tL, 33, w, 1.f);
}

// ---- post math: split partials -> layer output x (lane=dim) ----------------
__device__ __forceinline__ float post_math(int row, int lane)
{
    float nom = 0.f, den = 0.f, alp = 0.f;
#pragma unroll
    for (int s = 0; s < KSPLIT; ++s) {
        const float* pr = g_Pp + ((size_t)s * N + row) * NC1;
        nom += pr[lane]; den += pr[32]; alp += pr[33];
    }
    den = (den >= 0.f) ? fmaxf(den, 1e-10f) : fminf(den, -1e-10f);

    float v = nom / den;
    float vn = sqrtf(fmaxf(wsum(v * v), 1e-30f));
    float am = tanhf(0.5f * artanh_c(vn)) * (v / vn);
    float amn = sqrtf(fmaxf(wsum(am * am), 1e-30f));
    float axw = tanhf(alp * artanh_c(amn)) * (am / amn);
    float axwn = sqrtf(fmaxf(wsum(axw * axw), 1e-30f));
    float r = fmaxf(artanh_c(axwn) * (axw / axwn), 0.f);
    float rn = sqrtf(fmaxf(wsum(r * r), 1e-30f));
    return tanhf(rn) * (r / rn);
}

// ============================ layer-1 prep ==================================
__global__ void prep_kernel(const float* __restrict__ X0,
                            const float* __restrict__ W)
{
    __shared__ float Ws[D][D + 1];
    __shared__ __nv_bfloat16 tH[NC1][8], tL[NC1][8];
    const int tid = threadIdx.x;
    for (int i = tid; i < D * D; i += blockDim.x) Ws[i >> 5][i & 31] = W[i];
    __syncthreads();

    const int lane = tid & 31, w = tid >> 5;
    const int row0 = blockIdx.x * 8;
    prep_math(Ws, X0[(row0 + w) * D + lane], lane, w, tH, tL);
    store_cols_t<34>(tH, tL, tid, row0);
}

// ============================ fused post + prep (layer 2) ===================
__global__ void post_prep_kernel(const float* __restrict__ W)
{
    __shared__ float Ws[D][D + 1];
    __shared__ __nv_bfloat16 tH[NC1][8], tL[NC1][8];
    const int tid = threadIdx.x;
    for (int i = tid; i < D * D; i += blockDim.x) Ws[i >> 5][i & 31] = W[i];
    __syncthreads();

    const int lane = tid & 31, w = tid >> 5;
    const int row0 = blockIdx.x * 8;
    float x = post_math(row0 + w, lane);
    prep_math(Ws, x, lane, w, tH, tL);
    store_cols_t<34>(tH, tL, tid, row0);
}

// ============================ fused post + logits ===========================
__global__ void post_logits_kernel(const float* __restrict__ Wl,
                                   const float* __restrict__ pks)
{
    __shared__ float bs[C][D], ws[C][D];
    __shared__ float an_s[C], lam_s[C], b2_s[C];
    __shared__ __nv_bfloat16 tH[C][8], tL[C][8];
    const int tid = threadIdx.x;
    for (int i = tid; i < C * D; i += blockDim.x) {
        const int c = i >> 5, d = i & 31;
        bs[c][d] = pks[i];
        ws[c][d] = Wl[d * C + c];
    }
    __syncthreads();
    if (tid < C) {
        float s2 = 0.f, b2 = 0.f;
        for (int d = 0; d < D; ++d) { s2 += ws[tid][d] * ws[tid][d]; b2 += bs[tid][d] * bs[tid][d]; }
        an_s[tid] = fmaxf(sqrtf(s2), 1e-10f);
        b2_s[tid] = b2;
        lam_s[tid] = 2.f / fmaxf(1.f - b2, 1e-15f);
    }
    __syncthreads();

    const int lane = tid & 31, w = tid >> 5;
    const int row0 = blockIdx.x * 8;
    float x = post_math(row0 + w, lane);
    float y2 = wsum(x * x);

#pragma unroll 1
    for (int c = 0; c < C; ++c) {
        float bd = bs[c][lane];
        float bx = wsum(bd * x);
        float b2 = b2_s[c];
        float c1 = 1.f - 2.f * bx + y2;
        float c2 = 1.f - b2;
        float dd = fmaxf(1.f - 2.f * bx + b2 * y2, 1e-15f);
        float z = (c2 * x - c1 * bd) / dd;
        float za = wsum(z * ws[c][lane]);
        float zn = fmaxf(sqrtf(fmaxf(wsum(z * z), 1e-30f)), 1e-10f);
        float dist = asinhf(2.f * za / ((1.f - zn * zn) * an_s[c]));
        float lg = lam_s[c] * an_s[c] * dist;       // lane-uniform
        if (lane == 0) stage_hl(tH, tL, c, w, lg);
    }
    store_cols_t<C>(tH, tL, tid, row0);
}

// ============================ double-bf16 HMMA GEMM =========================
// P[split][r][c] = sum over k in split of A[r,k] * Mt[c][k]
// A,B hi/lo split; product = hiA*hiB + hiA*loB + loA*hiB.
// Double-buffered dynamic smem; one __syncthreads per tile.
template <int NT>
__global__ void __launch_bounds__(256, 2) gemm_mma(const float* __restrict__ A)
{
    constexpr int NR = NT * 8;         // B rows (output cols)
    constexpr int BU = NR * 8;         // uint4 chunks per B tile
    constexpr int BSTG = NR * PITCH;   // bf16 elems per B stage

    extern __shared__ __nv_bfloat16 dyn[];
    __nv_bfloat16* AsH = dyn;                   // 2 stages each
    __nv_bfloat16* AsL = AsH + 2 * ASTAGE;
    __nv_bfloat16* BsH = AsL + 2 * ASTAGE;
    __nv_bfloat16* BsL = BsH + 2 * BSTG;

    const int tid = threadIdx.x, wid = tid >> 5, lane = tid & 31;
    const int row0 = blockIdx.x * BM;
    const size_t kb0 = (size_t)blockIdx.y * (N / KSPLIT);

    const float4* af4 = reinterpret_cast<const float4*>(
        A + ((size_t)(row0 + (tid >> 4)) * N + kb0)) + (tid & 15);
    const char* bbH = reinterpret_cast<const char*>(g_MtH + kb0);
    const char* bbL = reinterpret_cast<const char*>(g_MtL + kb0);
    const size_t bo0 = (size_t)(tid >> 3) * N * 2 + (tid & 7) * 16;
    const size_t bo1 = (size_t)((tid + 256) >> 3) * N * 2 + (tid & 7) * 16;

    const int asOff = (tid >> 4) * PITCH + (tid & 15) * 4;
    const int bsOff0 = (tid >> 3) * PITCH + (tid & 7) * 8;
    const int bsOff1 = ((tid + 256) >> 3) * PITCH + (tid & 7) * 8;

    float acc[NT][4];
#pragma unroll
    for (int j = 0; j < NT; ++j)
#pragma unroll
        for (int q = 0; q < 4; ++q) acc[j][q] = 0.f;

    float4 ar[8];
    uint4 brH0, brH1, brL0, brL1;
#pragma unroll
    for (int p = 0; p < 8; ++p) ar[p] = af4[(size_t)p * 32768];
    brH0 = *reinterpret_cast<const uint4*>(bbH + bo0);
    brL0 = *reinterpret_cast<const uint4*>(bbL + bo0);
    if (BU > 256 && tid < BU - 256) {
        brH1 = *reinterpret_cast<const uint4*>(bbH + bo1);
        brL1 = *reinterpret_cast<const uint4*>(bbL + bo1);
    }

    for (int t = 0; t < TILES; ++t) {
        const int st = t & 1;
        __nv_bfloat16* aH = AsH + st * ASTAGE;
        __nv_bfloat16* aL = AsL + st * ASTAGE;
        __nv_bfloat16* bH = BsH + st * BSTG;
        __nv_bfloat16* bL = BsL + st * BSTG;

        // commit tile t: fp32 -> hi/lo bf16x2, 8B stores
#pragma unroll
        for (int p = 0; p < 8; ++p) {
            uint32_t h0, h1, l0, l1;
            asm("cvt.rn.bf16x2.f32 %0, %1, %2;" : "=r"(h0) : "f"(ar[p].y), "f"(ar[p].x));
            asm("cvt.rn.bf16x2.f32 %0, %1, %2;" : "=r"(h1) : "f"(ar[p].w), "f"(ar[p].z));
            float hx = __uint_as_float(h0 << 16);
            float hy = __uint_as_float(h0 & 0xFFFF0000u);
            float hz = __uint_as_float(h1 << 16);
            float hw = __uint_as_float(h1 & 0xFFFF0000u);
            asm("cvt.rn.bf16x2.f32 %0, %1, %2;" : "=r"(l0)
                : "f"(ar[p].y - hy), "f"(ar[p].x - hx));
            asm("cvt.rn.bf16x2.f32 %0, %1, %2;" : "=r"(l1)
                : "f"(ar[p].w - hw), "f"(ar[p].z - hz));
            *reinterpret_cast<uint2*>(&aH[asOff + p * 16 * PITCH]) = make_uint2(h0, h1);
            *reinterpret_cast<uint2*>(&aL[asOff + p * 16 * PITCH]) = make_uint2(l0, l1);
        }
        if (tid < BU) {
            *reinterpret_cast<uint4*>(&bH[bsOff0]) = brH0;
            *reinterpret_cast<uint4*>(&bL[bsOff0]) = brL0;
        }
        if (BU > 256 && tid < BU - 256) {
            *reinterpret_cast<uint4*>(&bH[bsOff1]) = brH1;
            *reinterpret_cast<uint4*>(&bL[bsOff1]) = brL1;
        }

        // prefetch tile t+1 into registers (no smem hazard)
        if (t + 1 < TILES) {
            const float4* ap = af4 + (size_t)(t + 1) * 16;
#pragma unroll
            for (int p = 0; p < 8; ++p) ar[p] = ap[(size_t)p * 32768];
            const size_t bshift = (size_t)(t + 1) * 128;
            brH0 = *reinterpret_cast<const uint4*>(bbH + bshift + bo0);
            brL0 = *reinterpret_cast<const uint4*>(bbL + bshift + bo0);
            if (BU > 256 && tid < BU - 256) {
                brH1 = *reinterpret_cast<const uint4*>(bbH + bshift + bo1);
                brL1 = *reinterpret_cast<const uint4*>(bbL + bshift + bo1);
            }
        }

        __syncthreads();   // tile t visible; prior-stage buffer freed safely

        // compute tile t: 4 k-steps, 3 products each
        const int aoff = (wid * 16 + (lane >> 2)) * PITCH + (lane & 3) * 2;
        const int boff = (lane >> 2) * PITCH + (lane & 3) * 2;
#pragma unroll
        for (int s = 0; s < 4; ++s) {
            uint32_t ah0 = *reinterpret_cast<const uint32_t*>(&aH[aoff + s * 16]);
            uint32_t ah1 = *reinterpret_cast<const uint32_t*>(&aH[aoff + s * 16 + 8 * PITCH]);
            uint32_t ah2 = *reinterpret_cast<const uint32_t*>(&aH[aoff + s * 16 + 8]);
            uint32_t ah3 = *reinterpret_cast<const uint32_t*>(&aH[aoff + s * 16 + 8 * PITCH + 8]);
            uint32_t al0 = *reinterpret_cast<const uint32_t*>(&aL[aoff + s * 16]);
            uint32_t al1 = *reinterpret_cast<const uint32_t*>(&aL[aoff + s * 16 + 8 * PITCH]);
            uint32_t al2 = *reinterpret_cast<const uint32_t*>(&aL[aoff + s * 16 + 8]);
            uint32_t al3 = *reinterpret_cast<const uint32_t*>(&aL[aoff + s * 16 + 8 * PITCH + 8]);
#pragma unroll
            for (int j = 0; j < NT; ++j) {
                uint32_t bh0 = *reinterpret_cast<const uint32_t*>(&bH[boff + j * 8 * PITCH + s * 16]);
                uint32_t bh1 = *reinterpret_cast<const uint32_t*>(&bH[boff + j * 8 * PITCH + s * 16 + 8]);
                uint32_t bl0 = *reinterpret_cast<const uint32_t*>(&bL[boff + j * 8 * PITCH + s * 16]);
                uint32_t bl1 = *reinterpret_cast<const uint32_t*>(&bL[boff + j * 8 * PITCH + s * 16 + 8]);
                asm volatile(
                    "mma.sync.aligned.m16n8k16.row.col.f32.bf16.bf16.f32 "
                    "{%0,%1,%2,%3}, {%4,%5,%6,%7}, {%8,%9}, {%0,%1,%2,%3};"
                    : "+f"(acc[j][0]), "+f"(acc[j][1]), "+f"(acc[j][2]), "+f"(acc[j][3])
                    : "r"(ah0), "r"(ah1), "r"(ah2), "r"(ah3), "r"(bl0), "r"(bl1));
                asm volatile(
                    "mma.sync.aligned.m16n8k16.row.col.f32.bf16.bf16.f32 "
                    "{%0,%1,%2,%3}, {%4,%5,%6,%7}, {%8,%9}, {%0,%1,%2,%3};"
                    : "+f"(acc[j][0]), "+f"(acc[j][1]), "+f"(acc[j][2]), "+f"(acc[j][3])
                    : "r"(al0), "r"(al1), "r"(al2), "r"(al3), "r"(bh0), "r"(bh1));
                asm volatile(
                    "mma.sync.aligned.m16n8k16.row.col.f32.bf16.bf16.f32 "
                    "{%0,%1,%2,%3}, {%4,%5,%6,%7}, {%8,%9}, {%0,%1,%2,%3};"
                    : "+f"(acc[j][0]), "+f"(acc[j][1]), "+f"(acc[j][2]), "+f"(acc[j][3])
                    : "r"(ah0), "r"(ah1), "r"(ah2), "r"(ah3), "r"(bh0), "r"(bh1));
            }
        }
    }

    // epilogue: write split partials (8B stores)
    float* Pg = (NT == 5) ? g_Pp : g_Po;
    constexpr int NOUT = NR;
    const int r0 = row0 + wid * 16 + (lane >> 2);
    const int cb = (lane & 3) * 2;
    float* base = Pg + (size_t)blockIdx.y * N * NOUT;
#pragma unroll
    for (int j = 0; j < NT; ++j) {
        *reinterpret_cast<float2*>(base + (size_t)r0 * NOUT + j * 8 + cb) =
            make_float2(acc[j][0], acc[j][1]);
        *reinterpret_cast<float2*>(base + (size_t)(r0 + 8) * NOUT + j * 8 + cb) =
            make_float2(acc[j][2], acc[j][3]);
    }
}

// ============================ final reduce ==================================
__global__ void reduce_kernel(float* __restrict__ out)
{
    const int i = blockIdx.x * blockDim.x + threadIdx.x;  // < N*C
    float s = 0.f;
#pragma unroll
    for (int k = 0; k < KSPLIT; ++k) s += g_Po[(size_t)k * N * C + i];
    out[i] = s;
}

// ============================ launch ========================================
extern "C" void kernel_launch(void* const* d_in, const int* in_sizes, int n_in,
                              void* d_out, int out_size)
{
    const float* X  = (const float*)d_in[0];
    const float* A  = (const float*)d_in[1];
    const float* W1 = (const float*)d_in[2];
    const float* W2 = (const float*)d_in[3];
    const float* Wl = (const float*)d_in[4];
    const float* pk = (const float*)d_in[5];

    const int smem5 = (4 * ASTAGE + 4 * 40 * PITCH) * 2;   // 96768 B
    const int smem2 = (4 * ASTAGE + 4 * 16 * PITCH) * 2;   // 82944 B
    cudaFuncSetAttribute((const void*)gemm_mma<5>,
                         cudaFuncAttributeMaxDynamicSharedMemorySize, smem5);
    cudaFuncSetAttribute((const void*)gemm_mma<2>,
                         cudaFuncAttributeMaxDynamicSharedMemorySize, smem2);

    const dim3 ggrid(N / BM, KSPLIT);   // (64, 4)
    const int rgrid = N / 8;            // 1024 blocks, warp-per-row

    prep_kernel<<<rgrid, 256>>>(X, W1);
    gemm_mma<5><<<ggrid, 256, smem5>>>(A);
    post_prep_kernel<<<rgrid, 256>>>(W2);
    gemm_mma<5><<<ggrid, 256, smem5>>>(A);
    post_logits_kernel<<<rgrid, 256>>>(Wl, pk);
    gemm_mma<2><<<ggrid, 256, smem2>>>(A);
    reduce_kernel<<<(N * C) / 256, 256>>>((float*)d_out);
}

// round 14
// speedup vs baseline: 2.3400x; 1.1345x over previous
#include <cuda_runtime.h>
#include <cuda_fp16.h>
#include <cstdint>

#define FULLMASK 0xffffffffu

constexpr int N = 8192, D = 32, C = 16;
constexpr int NC1 = 40;                   // stored cols for layer GEMMs (34 real)
constexpr int KSPLIT = 8;
constexpr int BM = 128, BK = 64;
constexpr int TILES = (N / KSPLIT) / BK;  // 16
constexpr int PITCH = 72;                 // smem row pitch in fp16 elems (144 B)
constexpr int ASTG = BM * PITCH;          // 9216 elems per A stage
constexpr int STAGES = 3;

// ---- scratch (static device arrays; zero-initialized, never allocated) ----
__device__ __align__(256) __nv_half g_Ah[(size_t)N * N];    // A * 16 in fp16 (128 MB)
__device__ __align__(256) __nv_half g_Mt[64 * N];           // M^T * 16; rows 34..63 stay 0
__device__ __align__(256) float g_Pp[KSPLIT * N * NC1];     // layer partials
__device__ __align__(256) float g_Po[KSPLIT * N * C];       // logits partials

__device__ __forceinline__ float wsum(float v) {
#pragma unroll
    for (int o = 16; o > 0; o >>= 1) v += __shfl_xor_sync(FULLMASK, v, o);
    return v;
}
__device__ __forceinline__ float artanh_c(float v) {
    v = fminf(fmaxf(v, -0.99999988f), 0.99999988f);
    return atanhf(v);
}

// ============================ A conversion pass =============================
// g_Ah = fp16(A * 16)  -- scale avoids fp16 denormals for A in [0, 3.7e-4]
__global__ void convA_kernel(const float4* __restrict__ A4)
{
    size_t i = (size_t)blockIdx.x * blockDim.x + threadIdx.x;   // < N*N/4
    float4 v = A4[i];
    union { __half2 h[2]; uint2 u; } cvt;
    cvt.h[0] = __floats2half2_rn(v.x * 16.f, v.y * 16.f);
    cvt.h[1] = __floats2half2_rn(v.z * 16.f, v.w * 16.f);
    reinterpret_cast<uint2*>(g_Ah)[i] = cvt.u;
}

// ---- staged transposed stores: [col][8 rows], flushed as 16B chunks --------
__device__ __forceinline__ void stage_h(__nv_half (*tB)[8], int col, int w, float v)
{
    tB[col][w] = __float2half_rn(v * 16.f);   // scale matches g_Ah; undone in epilogue
}
template <int NCOLS>
__device__ __forceinline__ void store_cols_t(__nv_half (*tB)[8], int tid, int row0)
{
    __syncthreads();
    if (tid < NCOLS)
        *reinterpret_cast<uint4*>(&g_Mt[(size_t)tid * N + row0]) =
            *reinterpret_cast<const uint4*>(&tB[tid][0]);
}

// ---- prep math: x (lane=dim) -> stage gamma*XW | gamma-1 | 1 ---------------
__device__ __forceinline__ void prep_math(const float (*Ws)[D + 1], float x,
                                          int lane, int w, __nv_half (*tB)[8])
{
    float xn = sqrtf(fmaxf(wsum(x * x), 1e-30f));
    float mx = 0.f;
#pragma unroll
    for (int d = 0; d < D; ++d)
        mx = fmaf(__shfl_sync(FULLMASK, x, d), Ws[d][lane], mx);
    float mxn = sqrtf(fmaxf(wsum(mx * mx), 1e-30f));
    float xw = tanhf(mxn / xn * artanh_c(xn)) / mxn * mx;
    float gamma = 2.f / fmaxf(1.f - wsum(xw * xw), 1e-15f);

    stage_h(tB, lane, w, gamma * xw);
    if (lane == 0) stage_h(tB, 32, w, gamma - 1.f);
    if (lane == 1) stage_h(tB, 33, w, 1.f);
}

// ---- post math: split partials -> layer output x (lane=dim) ----------------
__device__ __forceinline__ float post_math(int row, int lane)
{
    float nom = 0.f, den = 0.f, alp = 0.f;
#pragma unroll
    for (int s = 0; s < KSPLIT; ++s) {
        const float* pr = g_Pp + ((size_t)s * N + row) * NC1;
        nom += pr[lane]; den += pr[32]; alp += pr[33];
    }
    den = (den >= 0.f) ? fmaxf(den, 1e-10f) : fminf(den, -1e-10f);

    float v = nom / den;
    float vn = sqrtf(fmaxf(wsum(v * v), 1e-30f));
    float am = tanhf(0.5f * artanh_c(vn)) * (v / vn);
    float amn = sqrtf(fmaxf(wsum(am * am), 1e-30f));
    float axw = tanhf(alp * artanh_c(amn)) * (am / amn);
    float axwn = sqrtf(fmaxf(wsum(axw * axw), 1e-30f));
    float r = fmaxf(artanh_c(axwn) * (axw / axwn), 0.f);
    float rn = sqrtf(fmaxf(wsum(r * r), 1e-30f));
    return tanhf(rn) * (r / rn);
}

// ============================ layer-1 prep ==================================
__global__ void prep_kernel(const float* __restrict__ X0,
                            const float* __restrict__ W)
{
    __shared__ float Ws[D][D + 1];
    __shared__ __nv_half tB[NC1][8];
    const int tid = threadIdx.x;
    for (int i = tid; i < D * D; i += blockDim.x) Ws[i >> 5][i & 31] = W[i];
    __syncthreads();

    const int lane = tid & 31, w = tid >> 5;
    const int row0 = blockIdx.x * 8;
    prep_math(Ws, X0[(row0 + w) * D + lane], lane, w, tB);
    store_cols_t<34>(tB, tid, row0);
}

// ============================ fused post + prep (layer 2) ===================
__global__ void post_prep_kernel(const float* __restrict__ W)
{
    __shared__ float Ws[D][D + 1];
    __shared__ __nv_half tB[NC1][8];
    const int tid = threadIdx.x;
    for (int i = tid; i < D * D; i += blockDim.x) Ws[i >> 5][i & 31] = W[i];
    __syncthreads();

    const int lane = tid & 31, w = tid >> 5;
    const int row0 = blockIdx.x * 8;
    float x = post_math(row0 + w, lane);
    prep_math(Ws, x, lane, w, tB);
    store_cols_t<34>(tB, tid, row0);
}

// ============================ fused post + logits ===========================
__global__ void post_logits_kernel(const float* __restrict__ Wl,
                                   const float* __restrict__ pks)
{
    __shared__ float bs[C][D], ws[C][D];
    __shared__ float an_s[C], lam_s[C], b2_s[C];
    __shared__ __nv_half tB[C][8];
    const int tid = threadIdx.x;
    for (int i = tid; i < C * D; i += blockDim.x) {
        const int c = i >> 5, d = i & 31;
        bs[c][d] = pks[i];
        ws[c][d] = Wl[d * C + c];
    }
    __syncthreads();
    if (tid < C) {
        float s2 = 0.f, b2 = 0.f;
        for (int d = 0; d < D; ++d) { s2 += ws[tid][d] * ws[tid][d]; b2 += bs[tid][d] * bs[tid][d]; }
        an_s[tid] = fmaxf(sqrtf(s2), 1e-10f);
        b2_s[tid] = b2;
        lam_s[tid] = 2.f / fmaxf(1.f - b2, 1e-15f);
    }
    __syncthreads();

    const int lane = tid & 31, w = tid >> 5;
    const int row0 = blockIdx.x * 8;
    float x = post_math(row0 + w, lane);
    float y2 = wsum(x * x);

#pragma unroll 1
    for (int c = 0; c < C; ++c) {
        float bd = bs[c][lane];
        float bx = wsum(bd * x);
        float b2 = b2_s[c];
        float c1 = 1.f - 2.f * bx + y2;
        float c2 = 1.f - b2;
        float dd = fmaxf(1.f - 2.f * bx + b2 * y2, 1e-15f);
        float z = (c2 * x - c1 * bd) / dd;
        float za = wsum(z * ws[c][lane]);
        float zn = fmaxf(sqrtf(fmaxf(wsum(z * z), 1e-30f)), 1e-10f);
        float dist = asinhf(2.f * za / ((1.f - zn * zn) * an_s[c]));
        float lg = lam_s[c] * an_s[c] * dist;   // lane-uniform
        if (lane == 0) stage_h(tB, c, w, lg);
    }
    store_cols_t<C>(tB, tid, row0);
}

// ============================ fp16 HMMA GEMM (cp.async) =====================
// P[split][r][c] = (1/256) * sum over k in split of (16*A[r,k]) * (16*Mt[c][k])
// 3-stage cp.async pipeline, one __syncthreads per tile.
__device__ __forceinline__ void cpa16(uint32_t dst, const void* src) {
    asm volatile("cp.async.cg.shared.global [%0], [%1], 16;" :: "r"(dst), "l"(src));
}

template <int NT>
__global__ void __launch_bounds__(256, 3) gemm_mma()
{
    constexpr int NR = NT * 8;             // B rows (output cols)
    constexpr int BSTG = NR * PITCH;       // fp16 elems per B stage
    constexpr int STAGE_E = ASTG + BSTG;   // elems per stage
    constexpr int BOPS = NR * 8;           // 16B chunks per B tile

    extern __shared__ __nv_half dyn[];
    const uint32_t sbase = (uint32_t)__cvta_generic_to_shared(dyn);

    const int tid = threadIdx.x, wid = tid >> 5, lane = tid & 31;
    const int row0 = blockIdx.x * BM;
    const size_t kb0 = (size_t)blockIdx.y * (N / KSPLIT);

    const int ar = tid >> 3, ac = tid & 7;     // A: rows ar+32p, 16B chunk ac
    const __nv_half* aSrc = g_Ah + (size_t)(row0 + ar) * N + kb0 + ac * 8;
    const __nv_half* bSrc = g_Mt + kb0;

    float acc[NT][4];
#pragma unroll
    for (int j = 0; j < NT; ++j)
#pragma unroll
        for (int q = 0; q < 4; ++q) acc[j][q] = 0.f;

    // tile loader: stage s gets tile t
    auto load_tile = [&](int t, int s) {
        const uint32_t sb = sbase + s * STAGE_E * 2;
#pragma unroll
        for (int p = 0; p < 4; ++p)
            cpa16(sb + ((ar + 32 * p) * PITCH + ac * 8) * 2,
                  aSrc + (size_t)(32 * p) * N + t * BK);
#pragma unroll
        for (int i = tid; i < BOPS; i += 256) {
            const int brr = i >> 3, bcc = i & 7;
            cpa16(sb + (ASTG + brr * PITCH + bcc * 8) * 2,
                  bSrc + (size_t)brr * N + t * BK + bcc * 8);
        }
        asm volatile("cp.async.commit_group;" ::: "memory");
    };

    load_tile(0, 0);
    load_tile(1, 1);

    const int aoff = (wid * 16 + (lane >> 2)) * PITCH + (lane & 3) * 2;
    const int boff = (lane >> 2) * PITCH + (lane & 3) * 2;

    for (int t = 0; t < TILES; ++t) {
        asm volatile("cp.async.wait_group 1;" ::: "memory");   // tile t ready
        __syncthreads();                                        // all compute(t-1) done
        if (t + 2 < TILES) load_tile(t + 2, (t + 2) % STAGES);

        const __nv_half* aS = dyn + (t % STAGES) * STAGE_E;
        const __nv_half* bS = aS + ASTG;
#pragma unroll
        for (int s = 0; s < 4; ++s) {
            uint32_t a0 = *reinterpret_cast<const uint32_t*>(&aS[aoff + s * 16]);
            uint32_t a1 = *reinterpret_cast<const uint32_t*>(&aS[aoff + 8 * PITCH + s * 16]);
            uint32_t a2 = *reinterpret_cast<const uint32_t*>(&aS[aoff + s * 16 + 8]);
            uint32_t a3 = *reinterpret_cast<const uint32_t*>(&aS[aoff + 8 * PITCH + s * 16 + 8]);
#pragma unroll
            for (int j = 0; j < NT; ++j) {
                uint32_t b0 = *reinterpret_cast<const uint32_t*>(&bS[boff + j * 8 * PITCH + s * 16]);
                uint32_t b1 = *reinterpret_cast<const uint32_t*>(&bS[boff + j * 8 * PITCH + s * 16 + 8]);
                asm volatile(
                    "mma.sync.aligned.m16n8k16.row.col.f32.f16.f16.f32 "
                    "{%0,%1,%2,%3}, {%4,%5,%6,%7}, {%8,%9}, {%0,%1,%2,%3};"
                    : "+f"(acc[j][0]), "+f"(acc[j][1]), "+f"(acc[j][2]), "+f"(acc[j][3])
                    : "r"(a0), "r"(a1), "r"(a2), "r"(a3), "r"(b0), "r"(b1));
            }
        }
    }

    // epilogue: undo the 16*16 scaling, write split partials (8B stores)
    float* Pg = (NT == 5) ? g_Pp : g_Po;
    constexpr int NOUT = NR;
    const int r0 = row0 + wid * 16 + (lane >> 2);
    const int cb = (lane & 3) * 2;
    float* base = Pg + (size_t)blockIdx.y * N * NOUT;
    const float sc = 1.f / 256.f;
#pragma unroll
    for (int j = 0; j < NT; ++j) {
        *reinterpret_cast<float2*>(base + (size_t)r0 * NOUT + j * 8 + cb) =
            make_float2(acc[j][0] * sc, acc[j][1] * sc);
        *reinterpret_cast<float2*>(base + (size_t)(r0 + 8) * NOUT + j * 8 + cb) =
            make_float2(acc[j][2] * sc, acc[j][3] * sc);
    }
}

// ============================ final reduce ==================================
__global__ void reduce_kernel(float* __restrict__ out)
{
    const int i = blockIdx.x * blockDim.x + threadIdx.x;  // < N*C
    float s = 0.f;
#pragma unroll
    for (int k = 0; k < KSPLIT; ++k) s += g_Po[(size_t)k * N * C + i];
    out[i] = s;
}

// ============================ launch ========================================
extern "C" void kernel_launch(void* const* d_in, const int* in_sizes, int n_in,
                              void* d_out, int out_size)
{
    const float* X  = (const float*)d_in[0];
    const float* A  = (const float*)d_in[1];
    const float* W1 = (const float*)d_in[2];
    const float* W2 = (const float*)d_in[3];
    const float* Wl = (const float*)d_in[4];
    const float* pk = (const float*)d_in[5];

    const int smem5 = STAGES * (ASTG + 40 * PITCH) * 2;   // 72576 B
    const int smem2 = STAGES * (ASTG + 16 * PITCH) * 2;   // 62208 B
    cudaFuncSetAttribute((const void*)gemm_mma<5>,
                         cudaFuncAttributeMaxDynamicSharedMemorySize, smem5);
    cudaFuncSetAttribute((const void*)gemm_mma<2>,
                         cudaFuncAttributeMaxDynamicSharedMemorySize, smem2);

    const dim3 ggrid(N / BM, KSPLIT);   // (64, 8)
    const int rgrid = N / 8;            // 1024 blocks, warp-per-row

    convA_kernel<<<(N / 256) * (N / 4), 256>>>((const float4*)A);   // 65536 blocks
    prep_kernel<<<rgrid, 256>>>(X, W1);
    gemm_mma<5><<<ggrid, 256, smem5>>>();
    post_prep_kernel<<<rgrid, 256>>>(W2);
    gemm_mma<5><<<ggrid, 256, smem5>>>();
    post_logits_kernel<<<rgrid, 256>>>(Wl, pk);
    gemm_mma<2><<<ggrid, 256, smem2>>>();
    reduce_kernel<<<(N * C) / 256, 256>>>((float*)d_out);
}